// round 13
// baseline (speedup 1.0000x reference)
#include <cuda_runtime.h>
#include <cuda_fp16.h>
#include <cstdint>

// ---------------------------------------------------------------------------
// Problem constants
// ---------------------------------------------------------------------------
#define IN_DIM   4096
#define OUT_DIM  4096
#define RANK     16
#define M_TOTAL  8192                 // BATCH(4) * SEQ(2048)

// GEMM tiling: 128x128 CTA tile, 2 CTAs/SM for 4 warps/SMSP.
#define BM 128
#define BN 128
#define BK 64                         // fp16 per chunk (128 bytes per row)
#define NCH (IN_DIM / BK)             // 64 chunks per tile
#define STAGES 3

#define A_ST_BYTES (BM * 128)         // 16 KB
#define B_ST_BYTES (BN * 128)         // 16 KB
#define ST_BYTES   (A_ST_BYTES + B_ST_BYTES)          // 32 KB
#define SMEM_TOTAL (STAGES * ST_BYTES)                // 96 KB

#define N_MTILES (M_TOTAL / BM)       // 64
#define N_NTILES (OUT_DIM / BN)       // 32

// Packed fp16 operands in global scratch.
__device__ __align__(128) __half g_A[(size_t)M_TOTAL * IN_DIM];
__device__ __align__(128) __half g_B[(size_t)OUT_DIM * IN_DIM];

// ---------------------------------------------------------------------------
// Helpers
// ---------------------------------------------------------------------------
__device__ __forceinline__ uint32_t smem_u32(const void* p) {
    uint32_t a;
    asm("{ .reg .u64 t; cvta.to.shared.u64 t, %1; cvt.u32.u64 %0, t; }" : "=r"(a) : "l"(p));
    return a;
}

__device__ __forceinline__ uint32_t swz128(uint32_t off) {
    return off ^ ((off >> 3) & 0x70);
}

__device__ __forceinline__ void cp16(uint32_t dst, const void* src) {
    asm volatile("cp.async.cg.shared.global [%0], [%1], 16;" :: "r"(dst), "l"(src));
}
#define CP_COMMIT() asm volatile("cp.async.commit_group;" ::: "memory")
#define CP_WAIT1()  asm volatile("cp.async.wait_group 1;" ::: "memory")

#define LDSM4(r0, r1, r2, r3, addr) \
    asm volatile("ldmatrix.sync.aligned.m8n8.x4.shared.b16 {%0,%1,%2,%3}, [%4];" \
                 : "=r"(r0), "=r"(r1), "=r"(r2), "=r"(r3) : "r"(addr))

__device__ __forceinline__ void mma16816(float* d, const uint32_t* a,
                                         uint32_t b0, uint32_t b1) {
    asm volatile(
        "mma.sync.aligned.m16n8k16.row.col.f32.f16.f16.f32 "
        "{%0,%1,%2,%3}, {%4,%5,%6,%7}, {%8,%9}, {%0,%1,%2,%3};"
        : "+f"(d[0]), "+f"(d[1]), "+f"(d[2]), "+f"(d[3])
        : "r"(a[0]), "r"(a[1]), "r"(a[2]), "r"(a[3]), "r"(b0), "r"(b1));
}

// ---------------------------------------------------------------------------
// Pack x -> fp16 (no smem -> full occupancy, DRAM-bound)
// ---------------------------------------------------------------------------
__global__ __launch_bounds__(256)
void pack_x_kernel(const float* __restrict__ x)
{
    const size_t idx = ((size_t)blockIdx.x * 256 + threadIdx.x) * 4;
    const float4 v = *(const float4*)&x[idx];
    __half2 p0 = __floats2half2_rn(v.x, v.y);
    __half2 p1 = __floats2half2_rn(v.z, v.w);
    *(uint2*)&g_A[idx] = make_uint2(*(uint32_t*)&p0, *(uint32_t*)&p1);
}

// ---------------------------------------------------------------------------
// Merge weights -> fp16: g_B = f16(W + (w1a@w1b).*(w2a@w2b)*scalar)
// ---------------------------------------------------------------------------
__global__ __launch_bounds__(256)
void pack_w_kernel(const float* __restrict__ W,
                   const float* __restrict__ w1a, const float* __restrict__ w1b,
                   const float* __restrict__ w2a, const float* __restrict__ w2b,
                   const float* __restrict__ scalar_p)
{
    __shared__ float a1s[16][RANK];
    __shared__ float a2s[16][RANK];
    __shared__ float b1s[RANK][256];
    __shared__ float b2s[RANK][256];

    const int i0 = blockIdx.x * 256;
    const int o0 = blockIdx.y * 16;
    const int t  = threadIdx.x;

    {
        const int oo = t >> 4;
        const int r  = t & 15;
        a1s[oo][r] = w1a[(size_t)(o0 + oo) * RANK + r];
        a2s[oo][r] = w2a[(size_t)(o0 + oo) * RANK + r];
    }
    #pragma unroll
    for (int r = 0; r < RANK; r++) {
        b1s[r][t] = w1b[(size_t)r * IN_DIM + i0 + t];
        b2s[r][t] = w2b[(size_t)r * IN_DIM + i0 + t];
    }
    __syncthreads();

    const float s = *scalar_p;

    #pragma unroll 4
    for (int oo = 0; oo < 16; oo++) {
        float acc1 = 0.f, acc2 = 0.f;
        #pragma unroll
        for (int r = 0; r < RANK; r++) {
            acc1 = fmaf(a1s[oo][r], b1s[r][t], acc1);
            acc2 = fmaf(a2s[oo][r], b2s[r][t], acc2);
        }
        const size_t idx = (size_t)(o0 + oo) * IN_DIM + i0 + t;
        g_B[idx] = __float2half_rn(W[idx] + acc1 * acc2 * s);
    }
}

// ---------------------------------------------------------------------------
// Main GEMM: C[m][n] = sum_k A[m][k]*B[n][k] + bias[n]
// 128x128 CTA tile, 8 warps (2x4 grid of 64x32 warp tiles), 3-stage pipe,
// 2 CTAs/SM. Swizzled LDSM bases hoisted; k-step offset combined with XOR
// (pre-swizzle offsets have bits 5-6 clear, so swz(x+k) == swz(x)^k).
// ---------------------------------------------------------------------------
__global__ __launch_bounds__(256, 2)
void hgemm_kernel(const float* __restrict__ bias, float* __restrict__ C)
{
    extern __shared__ char smem[];
    const uint32_t sb = smem_u32(smem);

    const int t    = threadIdx.x;
    const int wid  = t >> 5;
    const int lane = t & 31;
    const int nt   = blockIdx.x;       // 0..31
    const int mt   = blockIdx.y;       // 0..63

    const int r0 = t >> 3;             // 0..31  (row base)
    const int c0 = t & 7;              // 0..7   (16B segment within row)

    const __half* Abase = g_A + (size_t)(mt * BM) * IN_DIM;
    const __half* Bbase = g_B + (size_t)(nt * BN) * IN_DIM;

    auto issue = [&](int c, int st) {
        const int k0 = c * BK;
        const uint32_t aB = sb + (uint32_t)st * ST_BYTES;
        const uint32_t bB = aB + A_ST_BYTES;
        const __half* As = Abase + k0;
        const __half* Bs = Bbase + k0;
        #pragma unroll
        for (int i = 0; i < 4; i++) {
            const int row = r0 + i * 32;
            const uint32_t so = swz128((uint32_t)(row * 128 + c0 * 16));
            cp16(aB + so, As + (size_t)row * IN_DIM + c0 * 8);
            cp16(bB + so, Bs + (size_t)row * IN_DIM + c0 * 8);
        }
        CP_COMMIT();
    };

    // prologue: 2 stages in flight
    issue(0, 0);
    issue(1, 1);

    const int wr = (wid >> 2) * 64;     // warp m offset (0 or 64)
    const int wc = (wid & 3) * 32;      // warp n offset (0,32,64,96)
    const int l15 = lane & 15;
    const int l16 = lane >> 4;

    // Hoisted swizzled bases (relative to stage start). Pre-swizzle offsets
    // have bits 5-6 == 0, so the per-ks offset combines via XOR below.
    uint32_t aSw[4], bSw[2];
    #pragma unroll
    for (int mf = 0; mf < 4; mf++)
        aSw[mf] = swz128((uint32_t)((wr + l15) * 128 + l16 * 16 + mf * 2048));
    #pragma unroll
    for (int nf = 0; nf < 2; nf++)
        bSw[nf] = swz128((uint32_t)((wc + l15) * 128 + l16 * 16 + nf * 2048))
                  + A_ST_BYTES;   // bit 14 only: doesn't collide with XOR bits

    float acc[4][4][4];
    #pragma unroll
    for (int i = 0; i < 4; i++)
        #pragma unroll
        for (int j = 0; j < 4; j++)
            #pragma unroll
            for (int q = 0; q < 4; q++)
                acc[i][j][q] = 0.f;

    for (int c = 0; c < NCH; c++) {
        CP_WAIT1();
        __syncthreads();

        if (c + 2 < NCH) issue(c + 2, (c + 2) % STAGES);
        else             CP_COMMIT();   // dummy: keep wait depth uniform

        const uint32_t stB = sb + (uint32_t)(c % STAGES) * ST_BYTES;

        #pragma unroll
        for (int ks = 0; ks < 4; ks++) {
            const uint32_t kadd = (uint32_t)(ks * 32);   // bits 5-6 -> XOR-safe
            uint32_t a[4][4];
            uint32_t b[2][4];
            // issue order: first MMA group's operands (a0, b0, b1) first
            LDSM4(a[0][0], a[0][1], a[0][2], a[0][3], stB + (aSw[0] ^ kadd));
            LDSM4(b[0][0], b[0][1], b[0][2], b[0][3], stB + (bSw[0] ^ kadd));
            LDSM4(b[1][0], b[1][1], b[1][2], b[1][3], stB + (bSw[1] ^ kadd));
            LDSM4(a[1][0], a[1][1], a[1][2], a[1][3], stB + (aSw[1] ^ kadd));
            LDSM4(a[2][0], a[2][1], a[2][2], a[2][3], stB + (aSw[2] ^ kadd));
            LDSM4(a[3][0], a[3][1], a[3][2], a[3][3], stB + (aSw[3] ^ kadd));
            #pragma unroll
            for (int mf = 0; mf < 4; mf++)
                #pragma unroll
                for (int nf = 0; nf < 2; nf++) {
                    mma16816(acc[mf][2 * nf],     a[mf], b[nf][0], b[nf][2]);
                    mma16816(acc[mf][2 * nf + 1], a[mf], b[nf][1], b[nf][3]);
                }
        }
    }

    // epilogue
    const int l4 = lane >> 2;
    const int l3 = lane & 3;
    #pragma unroll
    for (int mf = 0; mf < 4; mf++) {
        const int mrow = mt * BM + wr + mf * 16 + l4;
        #pragma unroll
        for (int nf = 0; nf < 4; nf++) {
            const int n = nt * BN + wc + nf * 8 + l3 * 2;
            const float2 bv = *(const float2*)&bias[n];
            float2 o0, o1;
            o0.x = acc[mf][nf][0] + bv.x;
            o0.y = acc[mf][nf][1] + bv.y;
            o1.x = acc[mf][nf][2] + bv.x;
            o1.y = acc[mf][nf][3] + bv.y;
            *(float2*)&C[(size_t)mrow * OUT_DIM + n] = o0;
            *(float2*)&C[(size_t)(mrow + 8) * OUT_DIM + n] = o1;
        }
    }
}

// ---------------------------------------------------------------------------
// Launch
// ---------------------------------------------------------------------------
extern "C" void kernel_launch(void* const* d_in, const int* in_sizes, int n_in,
                              void* d_out, int out_size)
{
    const float* x      = (const float*)d_in[0];
    const float* org_w  = (const float*)d_in[1];
    const float* org_b  = (const float*)d_in[2];
    const float* w1a    = (const float*)d_in[3];
    const float* w1b    = (const float*)d_in[4];
    const float* w2a    = (const float*)d_in[5];
    const float* w2b    = (const float*)d_in[6];
    const float* scalar = (const float*)d_in[7];
    float*       out    = (float*)d_out;
    (void)in_sizes; (void)n_in; (void)out_size;

    static bool attr_set = false;
    if (!attr_set) {
        cudaFuncSetAttribute(hgemm_kernel,
                             cudaFuncAttributeMaxDynamicSharedMemorySize, SMEM_TOTAL);
        attr_set = true;
    }

    pack_x_kernel<<<(M_TOTAL * (size_t)IN_DIM) / (256 * 4), 256>>>(x);
    pack_w_kernel<<<dim3(IN_DIM / 256, OUT_DIM / 16), 256>>>(org_w, w1a, w1b, w2a, w2b, scalar);
    hgemm_kernel<<<dim3(N_NTILES, N_MTILES), 256, SMEM_TOTAL>>>(org_b, out);
}

// round 14
// speedup vs baseline: 1.0491x; 1.0491x over previous
#include <cuda_runtime.h>
#include <cuda_fp16.h>
#include <cstdint>

// ---------------------------------------------------------------------------
// Problem constants
// ---------------------------------------------------------------------------
#define IN_DIM   4096
#define OUT_DIM  4096
#define RANK     16
#define M_TOTAL  8192                 // BATCH(4) * SEQ(2048)

// GEMM tiling: 128x128 CTA tile, 2 CTAs/SM for 4 warps/SMSP.
#define BM 128
#define BN 128
#define BK 64                         // fp16 per chunk (128 bytes per row)
#define NCH (IN_DIM / BK)             // 64 chunks per tile
#define STAGES 3

#define A_ST_BYTES (BM * 128)         // 16 KB
#define B_ST_BYTES (BN * 128)         // 16 KB
#define ST_BYTES   (A_ST_BYTES + B_ST_BYTES)          // 32 KB
#define SMEM_TOTAL (STAGES * ST_BYTES)                // 96 KB

#define N_MTILES (M_TOTAL / BM)       // 64
#define N_NTILES (OUT_DIM / BN)       // 32

// Packed fp16 operands in global scratch.
__device__ __align__(128) __half g_A[(size_t)M_TOTAL * IN_DIM];
__device__ __align__(128) __half g_B[(size_t)OUT_DIM * IN_DIM];

// ---------------------------------------------------------------------------
// Helpers
// ---------------------------------------------------------------------------
__device__ __forceinline__ uint32_t smem_u32(const void* p) {
    uint32_t a;
    asm("{ .reg .u64 t; cvta.to.shared.u64 t, %1; cvt.u32.u64 %0, t; }" : "=r"(a) : "l"(p));
    return a;
}

__device__ __forceinline__ uint32_t swz128(uint32_t off) {
    return off ^ ((off >> 3) & 0x70);
}

__device__ __forceinline__ void cp16(uint32_t dst, const void* src) {
    asm volatile("cp.async.cg.shared.global [%0], [%1], 16;" :: "r"(dst), "l"(src));
}
#define CP_COMMIT() asm volatile("cp.async.commit_group;" ::: "memory")
#define CP_WAIT1()  asm volatile("cp.async.wait_group 1;" ::: "memory")

#define LDSM4(r0, r1, r2, r3, addr) \
    asm volatile("ldmatrix.sync.aligned.m8n8.x4.shared.b16 {%0,%1,%2,%3}, [%4];" \
                 : "=r"(r0), "=r"(r1), "=r"(r2), "=r"(r3) : "r"(addr))

__device__ __forceinline__ void mma16816(float* d, const uint32_t* a,
                                         uint32_t b0, uint32_t b1) {
    asm volatile(
        "mma.sync.aligned.m16n8k16.row.col.f32.f16.f16.f32 "
        "{%0,%1,%2,%3}, {%4,%5,%6,%7}, {%8,%9}, {%0,%1,%2,%3};"
        : "+f"(d[0]), "+f"(d[1]), "+f"(d[2]), "+f"(d[3])
        : "r"(a[0]), "r"(a[1]), "r"(a[2]), "r"(a[3]), "r"(b0), "r"(b1));
}

// ---------------------------------------------------------------------------
// Pack x -> fp16 (no smem -> full occupancy, DRAM-bound)
// ---------------------------------------------------------------------------
__global__ __launch_bounds__(256)
void pack_x_kernel(const float* __restrict__ x)
{
    const size_t idx = ((size_t)blockIdx.x * 256 + threadIdx.x) * 4;
    const float4 v = *(const float4*)&x[idx];
    __half2 p0 = __floats2half2_rn(v.x, v.y);
    __half2 p1 = __floats2half2_rn(v.z, v.w);
    *(uint2*)&g_A[idx] = make_uint2(*(uint32_t*)&p0, *(uint32_t*)&p1);
}

// ---------------------------------------------------------------------------
// Merge weights -> fp16: g_B = f16(W + (w1a@w1b).*(w2a@w2b)*scalar)
// ---------------------------------------------------------------------------
__global__ __launch_bounds__(256)
void pack_w_kernel(const float* __restrict__ W,
                   const float* __restrict__ w1a, const float* __restrict__ w1b,
                   const float* __restrict__ w2a, const float* __restrict__ w2b,
                   const float* __restrict__ scalar_p)
{
    __shared__ float a1s[16][RANK];
    __shared__ float a2s[16][RANK];
    __shared__ float b1s[RANK][256];
    __shared__ float b2s[RANK][256];

    const int i0 = blockIdx.x * 256;
    const int o0 = blockIdx.y * 16;
    const int t  = threadIdx.x;

    {
        const int oo = t >> 4;
        const int r  = t & 15;
        a1s[oo][r] = w1a[(size_t)(o0 + oo) * RANK + r];
        a2s[oo][r] = w2a[(size_t)(o0 + oo) * RANK + r];
    }
    #pragma unroll
    for (int r = 0; r < RANK; r++) {
        b1s[r][t] = w1b[(size_t)r * IN_DIM + i0 + t];
        b2s[r][t] = w2b[(size_t)r * IN_DIM + i0 + t];
    }
    __syncthreads();

    const float s = *scalar_p;

    #pragma unroll 4
    for (int oo = 0; oo < 16; oo++) {
        float acc1 = 0.f, acc2 = 0.f;
        #pragma unroll
        for (int r = 0; r < RANK; r++) {
            acc1 = fmaf(a1s[oo][r], b1s[r][t], acc1);
            acc2 = fmaf(a2s[oo][r], b2s[r][t], acc2);
        }
        const size_t idx = (size_t)(o0 + oo) * IN_DIM + i0 + t;
        g_B[idx] = __float2half_rn(W[idx] + acc1 * acc2 * s);
    }
}

// ---------------------------------------------------------------------------
// Main GEMM: C[m][n] = sum_k A[m][k]*B[n][k] + bias[n]
// 128x128 CTA tile, 8 warps (2x4 grid of 64x32 warp tiles), 3-stage pipe,
// 2 CTAs/SM. Inline swizzle (ptxas folds it); LDSM issue order puts the
// first MMA group's operands (a0, b0, b1) first.
// ---------------------------------------------------------------------------
__global__ __launch_bounds__(256, 2)
void hgemm_kernel(const float* __restrict__ bias, float* __restrict__ C)
{
    extern __shared__ char smem[];
    const uint32_t sb = smem_u32(smem);

    const int t    = threadIdx.x;
    const int wid  = t >> 5;
    const int lane = t & 31;
    const int nt   = blockIdx.x;       // 0..31
    const int mt   = blockIdx.y;       // 0..63

    const int r0 = t >> 3;             // 0..31  (row base)
    const int c0 = t & 7;              // 0..7   (16B segment within row)

    const __half* Abase = g_A + (size_t)(mt * BM) * IN_DIM;
    const __half* Bbase = g_B + (size_t)(nt * BN) * IN_DIM;

    auto issue = [&](int c, int st) {
        const int k0 = c * BK;
        const uint32_t aB = sb + (uint32_t)st * ST_BYTES;
        const uint32_t bB = aB + A_ST_BYTES;
        const __half* As = Abase + k0;
        const __half* Bs = Bbase + k0;
        #pragma unroll
        for (int i = 0; i < 4; i++) {
            const int row = r0 + i * 32;
            const uint32_t so = swz128((uint32_t)(row * 128 + c0 * 16));
            cp16(aB + so, As + (size_t)row * IN_DIM + c0 * 8);
            cp16(bB + so, Bs + (size_t)row * IN_DIM + c0 * 8);
        }
        CP_COMMIT();
    };

    // prologue: 2 stages in flight
    issue(0, 0);
    issue(1, 1);

    const int wr = (wid >> 2) * 64;     // warp m offset (0 or 64)
    const int wc = (wid & 3) * 32;      // warp n offset (0,32,64,96)
    const int l15 = lane & 15;
    const int l16 = lane >> 4;
    const uint32_t aoff0 = (uint32_t)((wr + l15) * 128 + l16 * 16);
    const uint32_t boff0 = (uint32_t)((wc + l15) * 128 + l16 * 16);

    float acc[4][4][4];
    #pragma unroll
    for (int i = 0; i < 4; i++)
        #pragma unroll
        for (int j = 0; j < 4; j++)
            #pragma unroll
            for (int q = 0; q < 4; q++)
                acc[i][j][q] = 0.f;

    for (int c = 0; c < NCH; c++) {
        CP_WAIT1();
        __syncthreads();

        if (c + 2 < NCH) issue(c + 2, (c + 2) % STAGES);
        else             CP_COMMIT();   // dummy: keep wait depth uniform

        const uint32_t aB = sb + (uint32_t)(c % STAGES) * ST_BYTES;
        const uint32_t bB = aB + A_ST_BYTES;

        #pragma unroll
        for (int ks = 0; ks < 4; ks++) {
            const uint32_t kadd = ks * 32;
            uint32_t a[4][4];
            uint32_t b[2][4];
            // issue order: first MMA group's operands (a0, b0, b1) first
            LDSM4(a[0][0], a[0][1], a[0][2], a[0][3],
                  aB + swz128(aoff0 + kadd));
            LDSM4(b[0][0], b[0][1], b[0][2], b[0][3],
                  bB + swz128(boff0 + kadd));
            LDSM4(b[1][0], b[1][1], b[1][2], b[1][3],
                  bB + swz128(boff0 + 2048 + kadd));
            #pragma unroll
            for (int mf = 1; mf < 4; mf++)
                LDSM4(a[mf][0], a[mf][1], a[mf][2], a[mf][3],
                      aB + swz128(aoff0 + mf * 2048 + kadd));
            #pragma unroll
            for (int mf = 0; mf < 4; mf++)
                #pragma unroll
                for (int nf = 0; nf < 2; nf++) {
                    mma16816(acc[mf][2 * nf],     a[mf], b[nf][0], b[nf][2]);
                    mma16816(acc[mf][2 * nf + 1], a[mf], b[nf][1], b[nf][3]);
                }
        }
    }

    // epilogue
    const int l4 = lane >> 2;
    const int l3 = lane & 3;
    #pragma unroll
    for (int mf = 0; mf < 4; mf++) {
        const int mrow = mt * BM + wr + mf * 16 + l4;
        #pragma unroll
        for (int nf = 0; nf < 4; nf++) {
            const int n = nt * BN + wc + nf * 8 + l3 * 2;
            const float2 bv = *(const float2*)&bias[n];
            float2 o0, o1;
            o0.x = acc[mf][nf][0] + bv.x;
            o0.y = acc[mf][nf][1] + bv.y;
            o1.x = acc[mf][nf][2] + bv.x;
            o1.y = acc[mf][nf][3] + bv.y;
            *(float2*)&C[(size_t)mrow * OUT_DIM + n] = o0;
            *(float2*)&C[(size_t)(mrow + 8) * OUT_DIM + n] = o1;
        }
    }
}

// ---------------------------------------------------------------------------
// Launch
// ---------------------------------------------------------------------------
extern "C" void kernel_launch(void* const* d_in, const int* in_sizes, int n_in,
                              void* d_out, int out_size)
{
    const float* x      = (const float*)d_in[0];
    const float* org_w  = (const float*)d_in[1];
    const float* org_b  = (const float*)d_in[2];
    const float* w1a    = (const float*)d_in[3];
    const float* w1b    = (const float*)d_in[4];
    const float* w2a    = (const float*)d_in[5];
    const float* w2b    = (const float*)d_in[6];
    const float* scalar = (const float*)d_in[7];
    float*       out    = (float*)d_out;
    (void)in_sizes; (void)n_in; (void)out_size;

    static bool attr_set = false;
    if (!attr_set) {
        cudaFuncSetAttribute(hgemm_kernel,
                             cudaFuncAttributeMaxDynamicSharedMemorySize, SMEM_TOTAL);
        attr_set = true;
    }

    pack_x_kernel<<<(M_TOTAL * (size_t)IN_DIM) / (256 * 4), 256>>>(x);
    pack_w_kernel<<<dim3(IN_DIM / 256, OUT_DIM / 16), 256>>>(org_w, w1a, w1b, w2a, w2b, scalar);
    hgemm_kernel<<<dim3(N_NTILES, N_MTILES), 256, SMEM_TOTAL>>>(org_b, out);
}